// round 5
// baseline (speedup 1.0000x reference)
#include <cuda_runtime.h>
#include <cstdint>

#define S_LEN 2048
#define D_MODEL 2048
#define NH 16
#define HDIM 128
#define CQ_DIM 96
#define CKV_DIM 512

// ---------------- scratch (static device memory; no allocations) ----------------
__device__ float g_cq[S_LEN * CQ_DIM];
__device__ float g_ckv[S_LEN * CKV_DIM];
__device__ float g_q[S_LEN * NH * HDIM];
__device__ float g_k[S_LEN * NH * HDIM];
__device__ float g_v[S_LEN * NH * HDIM];
__device__ float g_vt[S_LEN * NH * HDIM];
__device__ float g_attn[S_LEN * NH * HDIM];
__device__ float g_qc[NH * S_LEN * 384];                  // [h][s][qhi|qhi|qlo]
__device__ float g_kc[NH * S_LEN * 384];                  // [h][s][khi|klo|khi]
__device__ float g_logits[(long long)NH * S_LEN * S_LEN]; // 256 MB
// rounded copies of external inputs
__device__ float g_x[S_LEN * D_MODEL];
__device__ float g_wqd[CQ_DIM * D_MODEL];
__device__ float g_wqu[(NH * HDIM) * CQ_DIM];
__device__ float g_wkvd[CKV_DIM * D_MODEL];
__device__ float g_wku[(NH * HDIM) * CKV_DIM];
__device__ float g_wvu[(NH * HDIM) * CKV_DIM];
__device__ float g_wo[D_MODEL * (NH * HDIM)];

// ---------------- helpers ----------------
__device__ __forceinline__ uint32_t smem_u32(const void* p) {
    uint32_t a;
    asm("{ .reg .u64 t; cvta.to.shared.u64 t, %1; cvt.u32.u64 %0, t; }" : "=r"(a) : "l"(p));
    return a;
}
__device__ __forceinline__ float rtf32(float x) {
    uint32_t u;
    asm("cvt.rna.tf32.f32 %0, %1;" : "=r"(u) : "f"(x));
    return __uint_as_float(u);
}
__device__ __forceinline__ void split_hl(float f, float& hi, float& lo) {
    uint32_t h;
    asm("cvt.rna.tf32.f32 %0, %1;" : "=r"(h) : "f"(f));
    hi = __uint_as_float(h);
    lo = rtf32(f - hi);
}
#define CP_ASYNC(dst, src, sz) \
    asm volatile("cp.async.cg.shared.global [%0], [%1], 16, %2;" \
        :: "r"(dst), "l"(src), "r"(sz) : "memory")
#define CP_COMMIT() asm volatile("cp.async.commit_group;" ::: "memory")
#define CP_WAIT(n)  asm volatile("cp.async.wait_group %0;" :: "n"(n) : "memory")

__device__ __forceinline__ void mma_u(float* c, const uint32_t* a, const uint32_t* b) {
    asm volatile(
        "mma.sync.aligned.m16n8k8.row.col.f32.tf32.tf32.f32 "
        "{%0,%1,%2,%3}, {%4,%5,%6,%7}, {%8,%9}, {%0,%1,%2,%3};"
        : "+f"(c[0]), "+f"(c[1]), "+f"(c[2]), "+f"(c[3])
        : "r"(a[0]), "r"(a[1]), "r"(a[2]), "r"(a[3]), "r"(b[0]), "r"(b[1]));
}
__device__ __forceinline__ void ldsm_x4(uint32_t* r, uint32_t addr) {
    asm volatile("ldmatrix.sync.aligned.m8n8.x4.shared.b16 {%0,%1,%2,%3}, [%4];"
        : "=r"(r[0]), "=r"(r[1]), "=r"(r[2]), "=r"(r[3]) : "r"(addr));
}

// ---------------- tf32 mma.sync GEMM: C = A[M,K] @ B[N,K]^T (+bias) ----------------
// BM=128, BN=128, BK=32, 256 threads, 2-stage cp.async, ldmatrix fragment loads.
// Operands assumed pre-rounded to tf32 (RN). M % 128 == 0, K % 32 == 0.
#define LDT 36
#define TILE_FLOATS (128 * LDT)
#define STAGE_BYTES (2 * TILE_FLOATS * 4)
#define GEMM_SMEM (2 * STAGE_BYTES)

__global__ __launch_bounds__(256, 2) void gemm_mma(
    const float* __restrict__ Ab, const float* __restrict__ Bb,
    const float* __restrict__ bias, float* __restrict__ Cb,
    int N, int K, int lda, int ldb, int ldc,
    long long aBatch, long long bBatch, long long cBatch, int round_out)
{
    extern __shared__ char smem[];
    const uint32_t su = smem_u32(smem);

    const int tid = threadIdx.x;
    const int warp = tid >> 5;
    const int lane = tid & 31;
    const int wm = warp & 1;
    const int wn = warp >> 1;
    const float* A = Ab + (long long)blockIdx.z * aBatch;
    const float* B = Bb + (long long)blockIdx.z * bBatch;
    float* C = Cb + (long long)blockIdx.z * cBatch;
    const int bm0 = blockIdx.y * 128;
    const int bn0 = blockIdx.x * 128;

    // cp.async coordinates (4 float4 per thread per tile)
    int smoff[4];
    const float* aptr[4];
    const float* bptr[4];
    uint32_t bsz[4];
#pragma unroll
    for (int i = 0; i < 4; i++) {
        int idx = tid + i * 256;
        int r = idx >> 3;
        int c4 = idx & 7;
        smoff[i] = (r * LDT + c4 * 4) * 4;
        aptr[i] = A + (size_t)(bm0 + r) * lda + c4 * 4;
        bptr[i] = B + (size_t)(bn0 + r) * ldb + c4 * 4;
        bsz[i] = (bn0 + r < N) ? 16u : 0u;
    }

    // ldmatrix per-lane byte offsets
    // A x4 tiles (per mt): t = lane>>3; row = wm*64 + (t&1)*8 + (lane&7); col = (t>>1)*4
    const int a_off = ((wm * 64 + ((lane >> 3) & 1) * 8 + (lane & 7)) * LDT
                       + ((lane >> 4) << 2)) * 4;
    // B x4 tiles (per nt pair): row = wn*32 + pair*16 + (t>>1)*8 + (lane&7); col = (t&1)*4
    const int b_off = ((wn * 32 + ((lane >> 4) << 3) + (lane & 7)) * LDT
                       + (((lane >> 3) & 1) << 2)) * 4;

    float acc[4][4][4];
#pragma unroll
    for (int mt = 0; mt < 4; mt++)
#pragma unroll
        for (int nt = 0; nt < 4; nt++)
#pragma unroll
            for (int j = 0; j < 4; j++) acc[mt][nt][j] = 0.f;

    const int nsteps = K >> 5;
    {
        uint32_t sb = su;
#pragma unroll
        for (int i = 0; i < 4; i++) CP_ASYNC(sb + smoff[i], aptr[i], 16u);
#pragma unroll
        for (int i = 0; i < 4; i++) CP_ASYNC(sb + TILE_FLOATS * 4 + smoff[i], bptr[i], bsz[i]);
        CP_COMMIT();
    }

    for (int s = 0; s < nsteps; s++) {
        if (s + 1 < nsteps) {
            uint32_t sb = su + ((s + 1) & 1) * STAGE_BYTES;
            const int k0 = (s + 1) << 5;
#pragma unroll
            for (int i = 0; i < 4; i++) CP_ASYNC(sb + smoff[i], aptr[i] + k0, 16u);
#pragma unroll
            for (int i = 0; i < 4; i++) CP_ASYNC(sb + TILE_FLOATS * 4 + smoff[i], bptr[i] + k0, bsz[i]);
            CP_COMMIT();
            CP_WAIT(1);
        } else {
            CP_WAIT(0);
        }
        __syncthreads();

        const uint32_t sa = su + (s & 1) * STAGE_BYTES + a_off;
        const uint32_t sbb = su + (s & 1) * STAGE_BYTES + TILE_FLOATS * 4 + b_off;

#pragma unroll
        for (int kk = 0; kk < 4; kk++) {
            uint32_t a_regs[4][4], b_regs[2][4];
#pragma unroll
            for (int mt = 0; mt < 4; mt++)
                ldsm_x4(a_regs[mt], sa + (mt * 16 * LDT + kk * 8) * 4);
#pragma unroll
            for (int pr = 0; pr < 2; pr++)
                ldsm_x4(b_regs[pr], sbb + (pr * 16 * LDT + kk * 8) * 4);
#pragma unroll
            for (int mt = 0; mt < 4; mt++)
#pragma unroll
                for (int nt = 0; nt < 4; nt++)
                    mma_u(acc[mt][nt], a_regs[mt], &b_regs[nt >> 1][(nt & 1) * 2]);
        }
        __syncthreads();
    }

    const bool has_bias = (bias != nullptr);
    const int gr = lane >> 2;
    const int gc = lane & 3;
#pragma unroll
    for (int mt = 0; mt < 4; mt++) {
        int r0 = bm0 + wm * 64 + mt * 16 + gr;
#pragma unroll
        for (int nt = 0; nt < 4; nt++) {
            int c0 = bn0 + wn * 32 + nt * 8 + gc * 2;
            if (c0 < N) {
                float bx = has_bias ? bias[c0] : 0.f;
                float by = has_bias ? bias[c0 + 1] : 0.f;
                float v00 = acc[mt][nt][0] + bx, v01 = acc[mt][nt][1] + by;
                float v10 = acc[mt][nt][2] + bx, v11 = acc[mt][nt][3] + by;
                if (round_out) {
                    v00 = rtf32(v00); v01 = rtf32(v01);
                    v10 = rtf32(v10); v11 = rtf32(v11);
                }
                *(float2*)&C[(size_t)r0 * ldc + c0] = make_float2(v00, v01);
                *(float2*)&C[(size_t)(r0 + 8) * ldc + c0] = make_float2(v10, v11);
            }
        }
    }
}

// ---------------- round fp32 -> tf32(RN) elementwise ----------------
__global__ __launch_bounds__(256) void round_pass(
    const float* __restrict__ src, float* __restrict__ dst)
{
    int i = blockIdx.x * blockDim.x + threadIdx.x;
    float4 v = ((const float4*)src)[i];
    v.x = rtf32(v.x); v.y = rtf32(v.y); v.z = rtf32(v.z); v.w = rtf32(v.w);
    ((float4*)dst)[i] = v;
}

// ---------------- RoPE + hi/lo pack for the K=384 logits GEMM ----------------
// qc[h][s][0:128]=qhi, [128:256]=qhi, [256:384]=qlo    (q scaled by 1/sqrt(HD))
// kc[h][s][0:128]=khi, [128:256]=klo, [256:384]=khi
__global__ __launch_bounds__(256) void rope_pack(
    const float* __restrict__ q, const float* __restrict__ k,
    const float* __restrict__ cosb, const float* __restrict__ sinb,
    float* __restrict__ qc, float* __restrict__ kc)
{
    int idx = blockIdx.x * blockDim.x + threadIdx.x;
    int dh = idx & 63;
    int t = idx >> 6;
    int h = t & (NH - 1);
    int s = t >> 4;
    if (s >= S_LEN) return;

    float c1 = cosb[s * HDIM + dh];
    float s1 = sinb[s * HDIM + dh];
    float c2 = cosb[s * HDIM + dh + 64];
    float s2 = sinb[s * HDIM + dh + 64];

    size_t base = (size_t)s * (NH * HDIM) + h * HDIM + dh;
    const float sc = 0.08838834764831845f;  // 1/sqrt(128)

    float q1 = q[base], q2 = q[base + 64];
    float qa = (q1 * c1 - q2 * s1) * sc;
    float qb = (q2 * c2 + q1 * s2) * sc;
    float k1 = k[base], k2 = k[base + 64];
    float ka = k1 * c1 - k2 * s1;
    float kb = k2 * c2 + k1 * s2;

    float qah, qal, qbh, qbl, kah, kal, kbh, kbl;
    split_hl(qa, qah, qal); split_hl(qb, qbh, qbl);
    split_hl(ka, kah, kal); split_hl(kb, kbh, kbl);

    size_t ob = ((size_t)h * S_LEN + s) * 384 + dh;
    qc[ob]       = qah; qc[ob + 64]       = qbh;
    qc[ob + 128] = qah; qc[ob + 128 + 64] = qbh;
    qc[ob + 256] = qal; qc[ob + 256 + 64] = qbl;
    kc[ob]       = kah; kc[ob + 64]       = kbh;
    kc[ob + 128] = kal; kc[ob + 128 + 64] = kbl;
    kc[ob + 256] = kah; kc[ob + 256 + 64] = kbh;
}

// ---------------- row softmax over 2048-wide rows, in place; rounds output ----------------
__global__ __launch_bounds__(256) void softmax_rows(float* __restrict__ L)
{
    __shared__ float red[8];
    float* p = L + (size_t)blockIdx.x * 2048;
    const int tid = threadIdx.x;
    const int wid = tid >> 5;
    const int lid = tid & 31;

    float4 a = ((const float4*)p)[tid];
    float4 b = ((const float4*)p)[tid + 256];

    float mx = fmaxf(fmaxf(fmaxf(a.x, a.y), fmaxf(a.z, a.w)),
                     fmaxf(fmaxf(b.x, b.y), fmaxf(b.z, b.w)));
#pragma unroll
    for (int m = 16; m > 0; m >>= 1) mx = fmaxf(mx, __shfl_xor_sync(~0u, mx, m));
    if (lid == 0) red[wid] = mx;
    __syncthreads();
    if (wid == 0) {
        float v = red[lid & 7];
#pragma unroll
        for (int m = 4; m > 0; m >>= 1) v = fmaxf(v, __shfl_xor_sync(~0u, v, m));
        if (lid == 0) red[0] = v;
    }
    __syncthreads();
    mx = red[0];
    __syncthreads();

    a.x = __expf(a.x - mx); a.y = __expf(a.y - mx); a.z = __expf(a.z - mx); a.w = __expf(a.w - mx);
    b.x = __expf(b.x - mx); b.y = __expf(b.y - mx); b.z = __expf(b.z - mx); b.w = __expf(b.w - mx);
    float sm = a.x + a.y + a.z + a.w + b.x + b.y + b.z + b.w;
#pragma unroll
    for (int m = 16; m > 0; m >>= 1) sm += __shfl_xor_sync(~0u, sm, m);
    if (lid == 0) red[wid] = sm;
    __syncthreads();
    if (wid == 0) {
        float v = red[lid & 7];
#pragma unroll
        for (int m = 4; m > 0; m >>= 1) v += __shfl_xor_sync(~0u, v, m);
        if (lid == 0) red[0] = v;
    }
    __syncthreads();
    const float inv = 1.f / red[0];

    a.x = rtf32(a.x * inv); a.y = rtf32(a.y * inv); a.z = rtf32(a.z * inv); a.w = rtf32(a.w * inv);
    b.x = rtf32(b.x * inv); b.y = rtf32(b.y * inv); b.z = rtf32(b.z * inv); b.w = rtf32(b.w * inv);
    ((float4*)p)[tid] = a;
    ((float4*)p)[tid + 256] = b;
}

// ---------------- 2048x2048 transpose (v -> v^T), rounds output ----------------
__global__ void transpose2048(const float* __restrict__ src, float* __restrict__ dst)
{
    __shared__ float t[32][33];
    int x = threadIdx.x, y = threadIdx.y;
    int r0 = blockIdx.y * 32, c0 = blockIdx.x * 32;
#pragma unroll
    for (int i = 0; i < 32; i += 8)
        t[y + i][x] = src[(size_t)(r0 + y + i) * 2048 + c0 + x];
    __syncthreads();
#pragma unroll
    for (int i = 0; i < 32; i += 8)
        dst[(size_t)(c0 + y + i) * 2048 + r0 + x] = rtf32(t[x][y + i]);
}

// ---------------- launch ----------------
extern "C" void kernel_launch(void* const* d_in, const int* in_sizes, int n_in,
                              void* d_out, int out_size)
{
    const float* x        = (const float*)d_in[0];
    const float* rope_cos = (const float*)d_in[1];
    const float* rope_sin = (const float*)d_in[2];
    const float* wq_down  = (const float*)d_in[3];
    const float* bq_down  = (const float*)d_in[4];
    const float* wq_up    = (const float*)d_in[5];
    const float* bq_up    = (const float*)d_in[6];
    const float* wkv_down = (const float*)d_in[7];
    const float* bkv_down = (const float*)d_in[8];
    const float* wk_up    = (const float*)d_in[9];
    const float* bk_up    = (const float*)d_in[10];
    const float* wv_up    = (const float*)d_in[11];
    const float* bv_up    = (const float*)d_in[12];
    const float* wo       = (const float*)d_in[13];
    const float* bo       = (const float*)d_in[14];
    float* out = (float*)d_out;

    float *cq, *ckv, *q, *k, *v, *vt, *attn, *logits, *qc, *kc;
    float *rx, *rwqd, *rwqu, *rwkvd, *rwku, *rwvu, *rwo;
    cudaGetSymbolAddress((void**)&cq,     g_cq);
    cudaGetSymbolAddress((void**)&ckv,    g_ckv);
    cudaGetSymbolAddress((void**)&q,      g_q);
    cudaGetSymbolAddress((void**)&k,      g_k);
    cudaGetSymbolAddress((void**)&v,      g_v);
    cudaGetSymbolAddress((void**)&vt,     g_vt);
    cudaGetSymbolAddress((void**)&attn,   g_attn);
    cudaGetSymbolAddress((void**)&logits, g_logits);
    cudaGetSymbolAddress((void**)&qc,     g_qc);
    cudaGetSymbolAddress((void**)&kc,     g_kc);
    cudaGetSymbolAddress((void**)&rx,     g_x);
    cudaGetSymbolAddress((void**)&rwqd,   g_wqd);
    cudaGetSymbolAddress((void**)&rwqu,   g_wqu);
    cudaGetSymbolAddress((void**)&rwkvd,  g_wkvd);
    cudaGetSymbolAddress((void**)&rwku,   g_wku);
    cudaGetSymbolAddress((void**)&rwvu,   g_wvu);
    cudaGetSymbolAddress((void**)&rwo,    g_wo);

    cudaFuncSetAttribute(gemm_mma, cudaFuncAttributeMaxDynamicSharedMemorySize, GEMM_SMEM);

    const long long SS = (long long)S_LEN * S_LEN;
    const long long S384 = (long long)S_LEN * 384;

    // pre-round external GEMM operands to tf32 (RN)
    round_pass<<<(S_LEN * D_MODEL) / 1024, 256>>>(x, rx);
    round_pass<<<(CQ_DIM * D_MODEL) / 1024, 256>>>(wq_down, rwqd);
    round_pass<<<(NH * HDIM * CQ_DIM) / 1024, 256>>>(wq_up, rwqu);
    round_pass<<<(CKV_DIM * D_MODEL) / 1024, 256>>>(wkv_down, rwkvd);
    round_pass<<<(NH * HDIM * CKV_DIM) / 1024, 256>>>(wk_up, rwku);
    round_pass<<<(NH * HDIM * CKV_DIM) / 1024, 256>>>(wv_up, rwvu);
    round_pass<<<(D_MODEL * NH * HDIM) / 1024, 256>>>(wo, rwo);

    // c_q = x @ wq_down^T + b            [2048, 96]  (rounded out)
    gemm_mma<<<dim3(1, 16, 1), 256, GEMM_SMEM>>>(
        rx, rwqd, bq_down, cq, CQ_DIM, D_MODEL, D_MODEL, D_MODEL, CQ_DIM, 0, 0, 0, 1);
    // q = c_q @ wq_up^T + b              [2048, 2048] (raw fp32, pack splits it)
    gemm_mma<<<dim3(16, 16, 1), 256, GEMM_SMEM>>>(
        cq, rwqu, bq_up, q, 2048, CQ_DIM, CQ_DIM, CQ_DIM, 2048, 0, 0, 0, 0);
    // c_kv = x @ wkv_down^T + b          [2048, 512] (rounded out)
    gemm_mma<<<dim3(4, 16, 1), 256, GEMM_SMEM>>>(
        rx, rwkvd, bkv_down, ckv, CKV_DIM, D_MODEL, D_MODEL, D_MODEL, CKV_DIM, 0, 0, 0, 1);
    // k = c_kv @ wk_up^T + b             [2048, 2048] (raw fp32)
    gemm_mma<<<dim3(16, 16, 1), 256, GEMM_SMEM>>>(
        ckv, rwku, bk_up, k, 2048, CKV_DIM, CKV_DIM, CKV_DIM, 2048, 0, 0, 0, 0);
    // v = c_kv @ wv_up^T + b             [2048, 2048] (raw; transpose rounds)
    gemm_mma<<<dim3(16, 16, 1), 256, GEMM_SMEM>>>(
        ckv, rwvu, bv_up, v, 2048, CKV_DIM, CKV_DIM, CKV_DIM, 2048, 0, 0, 0, 0);

    // rope + hi/lo pack for K=384 logits GEMM
    rope_pack<<<(S_LEN * NH * 64) / 256, 256>>>(q, k, rope_cos, rope_sin, qc, kc);

    // logits[h] = Q'_h @ K'_h^T  (K=384 concat == tf32x3 precision, prec0 speed)
    gemm_mma<<<dim3(16, 16, NH), 256, GEMM_SMEM>>>(
        qc, kc, nullptr, logits, 2048, 384, 384, 384, 2048,
        S384, S384, SS, 0);

    // softmax rows (rounds output to tf32)
    softmax_rows<<<NH * S_LEN, 256>>>(logits);

    // v^T (rounds output)
    transpose2048<<<dim3(64, 64), dim3(32, 8)>>>(v, vt);

    // attn per head: M=2048, N=128, K=2048 (rounded out)
    gemm_mma<<<dim3(1, 16, NH), 256, GEMM_SMEM>>>(
        logits, vt, nullptr, attn, HDIM, 2048, 2048, 2048, 2048,
        SS, (long long)HDIM * 2048, HDIM, 1);

    // out = attn @ wo^T + bo             [2048, 2048] (full fp32 output)
    gemm_mma<<<dim3(16, 16, 1), 256, GEMM_SMEM>>>(
        attn, rwo, bo, out, 2048, 2048, 2048, 2048, 2048, 0, 0, 0, 0);
}